// round 15
// baseline (speedup 1.0000x reference)
#include <cuda_runtime.h>
#include <cuda_fp16.h>
#include <math.h>

#define NN 50000
#define EE 800000
#define RR 2000
#define FF 128
#define LDP 2
#define FDIM 384
#define PP 64

// ---------------- scratch ----------------
__device__ int    g_cnt[NN];
__device__ int    g_ptr[NN + 1];
__device__ int    g_cur[NN];
__device__ int    g_ssrc[EE];
__device__ int    g_srel[EE];
__device__ __half g_ent16[(size_t)NN * FF];
__device__ __half g_rel16[RR * FF];
__device__ __half g_relnorm16[RR * FF];
__device__ float  g_exps[2 * LDP * RR];
__device__ __half g_oute16[(size_t)NN * FDIM];
__device__ __half g_outr16[(size_t)NN * FDIM];
__device__ __half g_proxyn16[2][PP * FDIM];
__device__ __half g_proxyT16[2][FDIM * PP];
__device__ __half g_gate16T[2][FDIM * FDIM];
__device__ __half g_pf16[(size_t)2 * NN * FDIM];

// ---------------- helpers ----------------
__device__ __forceinline__ float warpSum(float v) {
#pragma unroll
    for (int o = 16; o; o >>= 1) v += __shfl_xor_sync(0xffffffffu, v, o);
    return v;
}
__device__ __forceinline__ float blockSum(float v, float* sh) {
    int lane = threadIdx.x & 31, w = threadIdx.x >> 5;
    v = warpSum(v);
    if (lane == 0) sh[w] = v;
    __syncthreads();
    if (threadIdx.x == 0) {
        int nw = (blockDim.x + 31) >> 5;
        float r = 0.f;
        for (int i = 0; i < nw; i++) r += sh[i];
        sh[0] = r;
    }
    __syncthreads();
    float r = sh[0];
    __syncthreads();
    return r;
}
__device__ __forceinline__ float ftanh(float x) {
    float y;
    asm("tanh.approx.f32 %0, %1;" : "=f"(y) : "f"(x));
    return y;
}
__device__ __forceinline__ float fsigmoid(float z) {
    return __fdividef(1.f, 1.f + __expf(-z));
}
__device__ __forceinline__ void mma_f16(float* c, const unsigned* a, const unsigned* b) {
    asm volatile(
        "mma.sync.aligned.m16n8k16.row.col.f32.f16.f16.f32 "
        "{%0,%1,%2,%3}, {%4,%5,%6,%7}, {%8,%9}, {%0,%1,%2,%3};"
        : "+f"(c[0]), "+f"(c[1]), "+f"(c[2]), "+f"(c[3])
        : "r"(a[0]), "r"(a[1]), "r"(a[2]), "r"(a[3]), "r"(b[0]), "r"(b[1]));
}
__device__ __forceinline__ unsigned smemA(const void* p) {
    return (unsigned)__cvta_generic_to_shared(p);
}
__device__ __forceinline__ float2 h2(const __half* p) {
    __half2 v = *(const __half2*)p;
    return __half22float2(v);
}
__device__ __forceinline__ void h8(const __half* p, float* f) {
    uint4 u = *(const uint4*)p;
    const __half2* h = (const __half2*)&u;
#pragma unroll
    for (int k = 0; k < 4; k++) {
        float2 t = __half22float2(h[k]);
        f[2 * k] = t.x;
        f[2 * k + 1] = t.y;
    }
}
__device__ __forceinline__ void sth8(__half* p, const float* f) {
    uint4 u;
    __half2* h = (__half2*)&u;
#pragma unroll
    for (int k = 0; k < 4; k++) h[k] = __floats2half2_rn(f[2 * k], f[2 * k + 1]);
    *(uint4*)p = u;
}
#define CP16(dst, src) asm volatile("cp.async.cg.shared.global [%0], [%1], 16;" ::"r"(dst), "l"(src))
#define CPCOMMIT() asm volatile("cp.async.commit_group;")
#define CPWAIT1() asm volatile("cp.async.wait_group 1;")
#define CPWAIT0() asm volatile("cp.async.wait_group 0;")

// ---------------- fused prep ----------------
__global__ void k_prep(const float* __restrict__ ent, const float* __restrict__ rel,
                       const float* __restrict__ Ge, const float* __restrict__ Gr) {
    int i = blockIdx.x * blockDim.x + threadIdx.x;
    if (i < NN) g_cnt[i] = 0;
    if (i < NN * FF) g_ent16[i] = __float2half_rn(ent[i]);
    if (i < RR * FF) g_rel16[i] = __float2half_rn(rel[i]);
    if (i < FDIM * FDIM) {
        int n = i / FDIM, k = i % FDIM;
        g_gate16T[0][i] = __float2half_rn(Ge[k * FDIM + n]);
        g_gate16T[1][i] = __float2half_rn(Gr[k * FDIM + n]);
    }
}

// ---------------- CSR build ----------------
__global__ void k_hist(const int* __restrict__ edst) {
    int e = blockIdx.x * blockDim.x + threadIdx.x;
    if (e < EE) atomicAdd(&g_cnt[edst[e]], 1);
}
__global__ void k_scan() {
    __shared__ int partial[1024];
    int tid = threadIdx.x;
    const int CH = 49;
    int base = tid * CH;
    int s = 0;
    for (int i = 0; i < CH; i++) {
        int idx = base + i;
        if (idx < NN) s += g_cnt[idx];
    }
    partial[tid] = s;
    __syncthreads();
    for (int off = 1; off < 1024; off <<= 1) {
        int v = (tid >= off) ? partial[tid - off] : 0;
        __syncthreads();
        partial[tid] += v;
        __syncthreads();
    }
    int run = (tid == 0) ? 0 : partial[tid - 1];
    for (int i = 0; i < CH; i++) {
        int idx = base + i;
        if (idx < NN) {
            g_ptr[idx] = run;
            g_cur[idx] = run;
            run += g_cnt[idx];
        }
    }
    if (tid == 0) g_ptr[NN] = EE;
}
__global__ void k_scatter(const int* __restrict__ esrc, const int* __restrict__ edst,
                          const int* __restrict__ erel) {
    int e = blockIdx.x * blockDim.x + threadIdx.x;
    if (e < EE) {
        int d = edst[e];
        int p = atomicAdd(&g_cur[d], 1);
        g_ssrc[p] = esrc[e];
        g_srel[p] = erel[e];
    }
}

// ---------------- per-relation: l2norm rows (fp16) + exp(score) tables ----------------
__global__ void k_relnorm(const float* __restrict__ rel_emb,
                          const float* __restrict__ attn_e,
                          const float* __restrict__ attn_r) {
    __shared__ float sh[32];
    int r = blockIdx.x, t = threadIdx.x;
    float v = rel_emb[r * FF + t];
    float s = blockSum(v * v, sh);
    float inv = 1.f / fmaxf(sqrtf(s), 1e-12f);
    float rn = v * inv;
    g_relnorm16[r * FF + t] = __float2half_rn(rn);
    float d0 = blockSum(rn * attn_e[t], sh);
    float d1 = blockSum(rn * attn_e[FF + t], sh);
    float d2 = blockSum(rn * attn_r[t], sh);
    float d3 = blockSum(rn * attn_r[FF + t], sh);
    if (t == 0) {
        g_exps[(0 * LDP + 0) * RR + r] = expf(d0);
        g_exps[(0 * LDP + 1) * RR + r] = expf(d1);
        g_exps[(1 * LDP + 0) * RR + r] = expf(d2);
        g_exps[(1 * LDP + 1) * RR + r] = expf(d3);
    }
}

// ---------------- proxy rows ----------------
__global__ void k_proxyn(const float* __restrict__ pe, const float* __restrict__ pr) {
    __shared__ float sh[32];
    int dual = blockIdx.x >> 6, p = blockIdx.x & 63, t = threadIdx.x;
    const float* src = dual ? pr : pe;
    float v = src[p * FDIM + t];
    float s = blockSum(v * v, sh);
    float inv = 1.f / fmaxf(sqrtf(s), 1e-12f);
    g_proxyn16[dual][p * FDIM + t] = __float2half_rn(v * inv);
    g_proxyT16[dual][t * PP + p] = __float2half_rn(v);
}

// ---------------- initial features: half-warp per edge, x2 unroll ----------------
__global__ void k_init() {
    int warp = threadIdx.x >> 5, lane = threadIdx.x & 31;
    int n = blockIdx.x * 8 + warp;
    if (n >= NN) return;
    int half = lane >> 4, sub = lane & 15;
    int beg = g_ptr[n], end = g_ptr[n + 1];
    float ae[8] = {}, ar[8] = {};
    int i = beg + half;
    for (; i + 2 < end; i += 4) {   // 2 edges per half per iter
        int s0 = g_ssrc[i], r0 = g_srel[i];
        int s1 = g_ssrc[i + 2], r1 = g_srel[i + 2];
        float a0[8], b0[8], a1[8], b1[8];
        h8(&g_ent16[(size_t)s0 * FF + sub * 8], a0);
        h8(&g_rel16[(size_t)r0 * FF + sub * 8], b0);
        h8(&g_ent16[(size_t)s1 * FF + sub * 8], a1);
        h8(&g_rel16[(size_t)r1 * FF + sub * 8], b1);
#pragma unroll
        for (int k = 0; k < 8; k++) {
            ae[k] += a0[k] + a1[k];
            ar[k] += b0[k] + b1[k];
        }
    }
    for (; i < end; i += 2) {
        int s = g_ssrc[i], r = g_srel[i];
        float a[8], b[8];
        h8(&g_ent16[(size_t)s * FF + sub * 8], a);
        h8(&g_rel16[(size_t)r * FF + sub * 8], b);
#pragma unroll
        for (int k = 0; k < 8; k++) { ae[k] += a[k]; ar[k] += b[k]; }
    }
#pragma unroll
    for (int k = 0; k < 8; k++) {
        ae[k] += __shfl_xor_sync(0xffffffffu, ae[k], 16);
        ar[k] += __shfl_xor_sync(0xffffffffu, ar[k], 16);
    }
    float inv = 1.f / fmaxf((float)(end - beg), 1.f);
    const float* src = half ? ar : ae;
    float o[8];
#pragma unroll
    for (int k = 0; k < 8; k++) o[k] = ftanh(src[k] * inv);
    __half* dst = (half ? g_outr16 : g_oute16) + (size_t)n * FDIM + sub * 8;
    sth8(dst, o);
}

// ---------------- GNN layer: half-warp per edge, 2 edges per half ----------------
__global__ void k_layer(int l) {
    int warp = threadIdx.x >> 5, lane = threadIdx.x & 31;
    int n = blockIdx.x * 8 + warp;
    if (n >= NN) return;
    int half = lane >> 4, sub = lane & 15;
    const float* __restrict__ exe = g_exps + (0 * LDP + l) * RR;
    const float* __restrict__ exr = g_exps + (1 * LDP + l) * RR;
    int beg = g_ptr[n], end = g_ptr[n + 1];
    int deg = end - beg;
    int iters = (deg + 3) >> 2;   // 4 edges per warp per iter, warp-uniform

    float acce[8] = {}, accr[8] = {};
    float se = 0.f, sr = 0.f;
    int co = l * FF + sub * 8;
    for (int it = 0; it < iters; it++) {
        int i0 = beg + 4 * it + half;       // edges: half, half+2 within quad
        int i1 = i0 + 2;
        bool v0 = i0 < end, v1 = i1 < end;
        int e0 = v0 ? i0 : (end - 1);
        int e1 = v1 ? i1 : (end - 1);
        int s0 = g_ssrc[e0], r0 = g_srel[e0];
        int s1 = g_ssrc[e1], r1 = g_srel[e1];
        float rn0[8], fe0[8], fr0[8], rn1[8], fe1[8], fr1[8];
        h8(&g_relnorm16[r0 * FF + sub * 8], rn0);
        h8(&g_oute16[(size_t)s0 * FDIM + co], fe0);
        h8(&g_outr16[(size_t)s0 * FDIM + co], fr0);
        h8(&g_relnorm16[r1 * FF + sub * 8], rn1);
        h8(&g_oute16[(size_t)s1 * FDIM + co], fe1);
        h8(&g_outr16[(size_t)s1 * FDIM + co], fr1);
        float de0 = 0.f, dr0 = 0.f, de1 = 0.f, dr1 = 0.f;
#pragma unroll
        for (int k = 0; k < 8; k++) {
            de0 += fe0[k] * rn0[k]; dr0 += fr0[k] * rn0[k];
            de1 += fe1[k] * rn1[k]; dr1 += fr1[k] * rn1[k];
        }
#pragma unroll
        for (int o = 1; o < 16; o <<= 1) {
            de0 += __shfl_xor_sync(0xffffffffu, de0, o);
            dr0 += __shfl_xor_sync(0xffffffffu, dr0, o);
            de1 += __shfl_xor_sync(0xffffffffu, de1, o);
            dr1 += __shfl_xor_sync(0xffffffffu, dr1, o);
        }
        float we0 = v0 ? exe[r0] : 0.f, wr0 = v0 ? exr[r0] : 0.f;
        float we1 = v1 ? exe[r1] : 0.f, wr1 = v1 ? exr[r1] : 0.f;
        se += we0 + we1; sr += wr0 + wr1;
        float ce0 = -2.f * de0, cr0 = -2.f * dr0;
        float ce1 = -2.f * de1, cr1 = -2.f * dr1;
#pragma unroll
        for (int k = 0; k < 8; k++) {
            acce[k] += we0 * fmaf(ce0, rn0[k], fe0[k]) + we1 * fmaf(ce1, rn1[k], fe1[k]);
            accr[k] += wr0 * fmaf(cr0, rn0[k], fr0[k]) + wr1 * fmaf(cr1, rn1[k], fr1[k]);
        }
    }
    // fold the two halves
#pragma unroll
    for (int k = 0; k < 8; k++) {
        acce[k] += __shfl_xor_sync(0xffffffffu, acce[k], 16);
        accr[k] += __shfl_xor_sync(0xffffffffu, accr[k], 16);
    }
    se += __shfl_xor_sync(0xffffffffu, se, 16);
    sr += __shfl_xor_sync(0xffffffffu, sr, 16);
    float ise = (se > 0.f) ? 1.f / se : 0.f;
    float isr = (sr > 0.f) ? 1.f / sr : 0.f;
    int off = (l + 1) * FF + sub * 8;
    float o[8];
    if (half == 0) {
#pragma unroll
        for (int k = 0; k < 8; k++) o[k] = ftanh(acce[k] * ise);
        sth8(&g_oute16[(size_t)n * FDIM + off], o);
    } else {
#pragma unroll
        for (int k = 0; k < 8; k++) o[k] = ftanh(accr[k] * isr);
        sth8(&g_outr16[(size_t)n * FDIM + off], o);
    }
}

// ================= fused GEMM1+GEMM2: attw stays in smem =================
#define G12_SMEM 64512

__global__ __launch_bounds__(256) void k_gemm12() {
    extern __shared__ __align__(16) char dsm[];
    __half(*As)[128][40] = (__half(*)[128][40])(dsm);
    __half(*Bs)[64][40] = (__half(*)[64][40])(dsm + 20480);
    __half(*attwS)[72] = (__half(*)[72])(dsm);
    float(*Ls)[66] = (float(*)[66])(dsm + 30720);
    __half(*BsP)[72] = (__half(*)[72])(dsm + 30720);

    int dual = blockIdx.z;
    int mb = blockIdx.x * 128;
    const __half* X16 = dual ? g_outr16 : g_oute16;
    const __half* Pn = g_proxyn16[dual];
    const __half* PT = g_proxyT16[dual];
    __half* pf16 = g_pf16 + (size_t)dual * NN * FDIM;
    int tid = threadIdx.x, lane = tid & 31, wid = tid >> 5;
    int g = lane >> 2, t4 = lane & 3;

    // ---- phase A: logits = invn*(X16 @ Pn^T), softmax -> attwS ----
    {
        int warpM = wid * 16;
        auto loadTiles = [&](int buf, int kc) {
#pragma unroll
            for (int i = 0; i < 2; i++) {
                int id = tid + i * 256;
                int row = id >> 2, cq = (id & 3) * 8;
                int gr = min(mb + row, NN - 1);
                CP16(smemA(&As[buf][row][cq]), &X16[(size_t)gr * FDIM + kc + cq]);
            }
            {
                int row = tid >> 2, cq = (tid & 3) * 8;
                CP16(smemA(&Bs[buf][row][cq]), &Pn[(size_t)row * FDIM + kc + cq]);
            }
            CPCOMMIT();
        };

        float acc[8][4] = {};
        float sq0 = 0.f, sq1 = 0.f;
        loadTiles(0, 0);
        const int NT = FDIM / 32;
        for (int t = 0; t < NT; t++) {
            int buf = t & 1;
            if (t + 1 < NT) { loadTiles(buf ^ 1, (t + 1) * 32); CPWAIT1(); }
            else CPWAIT0();
            __syncthreads();
#pragma unroll
            for (int ks = 0; ks < 2; ks++) {
                int k0 = ks * 16;
                unsigned a[4], b[8][2];
                a[0] = *(const unsigned*)&As[buf][warpM + g][k0 + 2 * t4];
                a[1] = *(const unsigned*)&As[buf][warpM + g + 8][k0 + 2 * t4];
                a[2] = *(const unsigned*)&As[buf][warpM + g][k0 + 2 * t4 + 8];
                a[3] = *(const unsigned*)&As[buf][warpM + g + 8][k0 + 2 * t4 + 8];
                {
                    float2 f0 = __half22float2(*(const __half2*)&a[0]);
                    float2 f1 = __half22float2(*(const __half2*)&a[1]);
                    float2 f2 = __half22float2(*(const __half2*)&a[2]);
                    float2 f3 = __half22float2(*(const __half2*)&a[3]);
                    sq0 += f0.x * f0.x + f0.y * f0.y + f2.x * f2.x + f2.y * f2.y;
                    sq1 += f1.x * f1.x + f1.y * f1.y + f3.x * f3.x + f3.y * f3.y;
                }
#pragma unroll
                for (int nt = 0; nt < 8; nt++) {
                    b[nt][0] = *(const unsigned*)&Bs[buf][nt * 8 + g][k0 + 2 * t4];
                    b[nt][1] = *(const unsigned*)&Bs[buf][nt * 8 + g][k0 + 2 * t4 + 8];
                }
#pragma unroll
                for (int nt = 0; nt < 8; nt++) mma_f16(acc[nt], a, b[nt]);
            }
            __syncthreads();
        }
#pragma unroll
        for (int o = 1; o < 4; o <<= 1) {
            sq0 += __shfl_xor_sync(0xffffffffu, sq0, o);
            sq1 += __shfl_xor_sync(0xffffffffu, sq1, o);
        }
        float i0 = 1.f / fmaxf(sqrtf(sq0), 1e-12f);
        float i1 = 1.f / fmaxf(sqrtf(sq1), 1e-12f);
#pragma unroll
        for (int nt = 0; nt < 8; nt++) {
            int r0 = warpM + g, r1 = warpM + g + 8, c0 = nt * 8 + t4 * 2;
            Ls[r0][c0] = acc[nt][0] * i0; Ls[r0][c0 + 1] = acc[nt][1] * i0;
            Ls[r1][c0] = acc[nt][2] * i1; Ls[r1][c0 + 1] = acc[nt][3] * i1;
        }
        __syncthreads();
        if (tid < 128) {
            float m = -3e38f;
            for (int c = 0; c < PP; c++) m = fmaxf(m, Ls[tid][c]);
            float s = 0.f;
            for (int c = 0; c < PP; c++) s += __expf(Ls[tid][c] - m);
            float is = __fdividef(1.f, s);
            for (int c = 0; c < PP; c++)
                attwS[tid][c] = __float2half_rn(__expf(Ls[tid][c] - m) * is);
        }
        __syncthreads();
    }

    // ---- phase B: pf16 = X16 - attwS @ proxy ----
    {
        int warpM = (wid & 3) * 32, warpN = (wid >> 2) * 64;
        for (int nc = 0; nc < 3; nc++) {
#pragma unroll
            for (int i = 0; i < 4; i++) {
                int id = tid + i * 256;
                int row = id >> 3, cq = (id & 7) * 8;
                CP16(smemA(&BsP[row][cq]), &PT[(size_t)(nc * 128 + row) * PP + cq]);
            }
            CPCOMMIT();
            CPWAIT0();
            __syncthreads();
            float acc[2][8][4] = {};
#pragma unroll
            for (int ks = 0; ks < 4; ks++) {
                int k0 = ks * 16;
                unsigned a[2][4], b[8][2];
#pragma unroll
                for (int mt = 0; mt < 2; mt++) {
                    int r = warpM + mt * 16;
                    a[mt][0] = *(const unsigned*)&attwS[r + g][k0 + 2 * t4];
                    a[mt][1] = *(const unsigned*)&attwS[r + g + 8][k0 + 2 * t4];
                    a[mt][2] = *(const unsigned*)&attwS[r + g][k0 + 2 * t4 + 8];
                    a[mt][3] = *(const unsigned*)&attwS[r + g + 8][k0 + 2 * t4 + 8];
                }
#pragma unroll
                for (int nt = 0; nt < 8; nt++) {
                    b[nt][0] = *(const unsigned*)&BsP[warpN + nt * 8 + g][k0 + 2 * t4];
                    b[nt][1] = *(const unsigned*)&BsP[warpN + nt * 8 + g][k0 + 2 * t4 + 8];
                }
#pragma unroll
                for (int mt = 0; mt < 2; mt++)
#pragma unroll
                    for (int nt = 0; nt < 8; nt++) mma_f16(acc[mt][nt], a[mt], b[nt]);
            }
#pragma unroll
            for (int mt = 0; mt < 2; mt++) {
#pragma unroll
                for (int nt = 0; nt < 8; nt++) {
                    int col = nc * 128 + warpN + nt * 8 + t4 * 2;
                    int r0 = mb + warpM + mt * 16 + g, r1 = r0 + 8;
                    if (r0 < NN) {
                        float2 x = h2(&X16[(size_t)r0 * FDIM + col]);
                        *(__half2*)&pf16[(size_t)r0 * FDIM + col] =
                            __floats2half2_rn(x.x - acc[mt][nt][0], x.y - acc[mt][nt][1]);
                    }
                    if (r1 < NN) {
                        float2 x = h2(&X16[(size_t)r1 * FDIM + col]);
                        *(__half2*)&pf16[(size_t)r1 * FDIM + col] =
                            __floats2half2_rn(x.x - acc[mt][nt][2], x.y - acc[mt][nt][3]);
                    }
                }
            }
            __syncthreads();
        }
    }
}

// GEMM3: gate = sigmoid(pf16@G + b); out = gate*X16 + (1-gate)*pf16.
__global__ __launch_bounds__(256) void k_gemm3t(const float* __restrict__ bias_e,
                                                const float* __restrict__ bias_r,
                                                float* __restrict__ out) {
    __shared__ __half As[2][128][40];
    __shared__ __half Bs[2][128][40];
    int dual = blockIdx.z;
    int mb = blockIdx.x * 128, nb = blockIdx.y * 128;
    const __half* X16 = dual ? g_outr16 : g_oute16;
    const __half* GT = g_gate16T[dual];
    const float* bias = dual ? bias_r : bias_e;
    const __half* pf16 = g_pf16 + (size_t)dual * NN * FDIM;
    int tid = threadIdx.x, lane = tid & 31, wid = tid >> 5;
    int g = lane >> 2, t4 = lane & 3;
    int warpM = (wid & 3) * 32, warpN = (wid >> 2) * 64;

    auto loadTiles = [&](int buf, int kc) {
#pragma unroll
        for (int i = 0; i < 2; i++) {
            int id = tid + i * 256;
            int row = id >> 2, cq = (id & 3) * 8;
            int gr = min(mb + row, NN - 1);
            CP16(smemA(&As[buf][row][cq]), &pf16[(size_t)gr * FDIM + kc + cq]);
        }
#pragma unroll
        for (int i = 0; i < 2; i++) {
            int id = tid + i * 256;
            int row = id >> 2, cq = (id & 3) * 8;
            CP16(smemA(&Bs[buf][row][cq]), &GT[(size_t)(nb + row) * FDIM + kc + cq]);
        }
        CPCOMMIT();
    };

    float acc[2][8][4] = {};
    loadTiles(0, 0);
    const int NT = FDIM / 32;
    for (int t = 0; t < NT; t++) {
        int buf = t & 1;
        if (t + 1 < NT) { loadTiles(buf ^ 1, (t + 1) * 32); CPWAIT1(); }
        else CPWAIT0();
        __syncthreads();
#pragma unroll
        for (int ks = 0; ks < 2; ks++) {
            int k0 = ks * 16;
            unsigned a[2][4], b[8][2];
#pragma unroll
            for (int mt = 0; mt < 2; mt++) {
                int r = warpM + mt * 16;
                a[mt][0] = *(const unsigned*)&As[buf][r + g][k0 + 2 * t4];
                a[mt][1] = *(const unsigned*)&As[buf][r + g + 8][k0 + 2 * t4];
                a[mt][2] = *(const unsigned*)&As[buf][r + g][k0 + 2 * t4 + 8];
                a[mt][3] = *(const unsigned*)&As[buf][r + g + 8][k0 + 2 * t4 + 8];
            }
#pragma unroll
            for (int nt = 0; nt < 8; nt++) {
                b[nt][0] = *(const unsigned*)&Bs[buf][warpN + nt * 8 + g][k0 + 2 * t4];
                b[nt][1] = *(const unsigned*)&Bs[buf][warpN + nt * 8 + g][k0 + 2 * t4 + 8];
            }
#pragma unroll
            for (int mt = 0; mt < 2; mt++)
#pragma unroll
                for (int nt = 0; nt < 8; nt++) mma_f16(acc[mt][nt], a[mt], b[nt]);
        }
        __syncthreads();
    }
#pragma unroll
    for (int mt = 0; mt < 2; mt++) {
#pragma unroll
        for (int nt = 0; nt < 8; nt++) {
            int col = nb + warpN + nt * 8 + t4 * 2;
            float b0 = bias[col], b1 = bias[col + 1];
            int r0 = mb + warpM + mt * 16 + g, r1 = r0 + 8;
            if (r0 < NN) {
                float g0 = fsigmoid(acc[mt][nt][0] + b0);
                float g1 = fsigmoid(acc[mt][nt][1] + b1);
                float2 x = h2(&X16[(size_t)r0 * FDIM + col]);
                float2 p = h2(&pf16[(size_t)r0 * FDIM + col]);
                float2 o = {g0 * x.x + (1.f - g0) * p.x, g1 * x.y + (1.f - g1) * p.y};
                *(float2*)&out[(size_t)r0 * (2 * FDIM) + dual * FDIM + col] = o;
            }
            if (r1 < NN) {
                float g0 = fsigmoid(acc[mt][nt][2] + b0);
                float g1 = fsigmoid(acc[mt][nt][3] + b1);
                float2 x = h2(&X16[(size_t)r1 * FDIM + col]);
                float2 p = h2(&pf16[(size_t)r1 * FDIM + col]);
                float2 o = {g0 * x.x + (1.f - g0) * p.x, g1 * x.y + (1.f - g1) * p.y};
                *(float2*)&out[(size_t)r1 * (2 * FDIM) + dual * FDIM + col] = o;
            }
        }
    }
}

// ---------------- launch ----------------
extern "C" void kernel_launch(void* const* d_in, const int* in_sizes, int n_in,
                              void* d_out, int out_size) {
    const float* ent     = (const float*)d_in[0];
    const float* rel     = (const float*)d_in[1];
    const int*   esrc    = (const int*)d_in[2];
    const int*   edst    = (const int*)d_in[3];
    const int*   erel    = (const int*)d_in[4];
    const float* attn_e  = (const float*)d_in[5];
    const float* gate_e  = (const float*)d_in[6];
    const float* proxy_e = (const float*)d_in[7];
    const float* bias_e  = (const float*)d_in[8];
    const float* attn_r  = (const float*)d_in[9];
    const float* gate_r  = (const float*)d_in[10];
    const float* proxy_r = (const float*)d_in[11];
    const float* bias_r  = (const float*)d_in[12];
    float* out = (float*)d_out;

    cudaFuncSetAttribute(k_gemm12, cudaFuncAttributeMaxDynamicSharedMemorySize, G12_SMEM);

    k_prep<<<25000, 256>>>(ent, rel, gate_e, gate_r);
    k_hist<<<3125, 256>>>(edst);
    k_scan<<<1, 1024>>>();
    k_scatter<<<3125, 256>>>(esrc, edst, erel);
    k_relnorm<<<RR, FF>>>(rel, attn_e, attn_r);
    k_init<<<6250, 256>>>();
    k_layer<<<6250, 256>>>(0);
    k_layer<<<6250, 256>>>(1);
    k_proxyn<<<128, FDIM>>>(proxy_e, proxy_r);
    k_gemm12<<<dim3(391, 1, 2), 256, G12_SMEM>>>();
    k_gemm3t<<<dim3(391, 3, 2), 256>>>(bias_e, bias_r, out);
}

// round 16
// speedup vs baseline: 1.0564x; 1.0564x over previous
#include <cuda_runtime.h>
#include <cuda_fp16.h>
#include <math.h>

#define NN 50000
#define EE 800000
#define RR 2000
#define FF 128
#define LDP 2
#define FDIM 384
#define PP 64

// ---------------- scratch ----------------
__device__ int    g_cnt[NN];
__device__ int    g_ptr[NN + 1];
__device__ int    g_cur[NN];
__device__ int    g_ssrc[EE];
__device__ int    g_srel[EE];
__device__ __half g_ent16[(size_t)NN * FF];
__device__ __half g_rel16[RR * FF];
__device__ __half g_relnorm16[RR * FF];
__device__ float  g_exps[2 * LDP * RR];
__device__ __half g_oute16[(size_t)NN * FDIM];
__device__ __half g_outr16[(size_t)NN * FDIM];
__device__ __half g_proxyn16[2][PP * FDIM];
__device__ __half g_proxyT16[2][FDIM * PP];
__device__ __half g_gate16T[2][FDIM * FDIM];
__device__ __half g_pf16[(size_t)2 * NN * FDIM];

// ---------------- helpers ----------------
__device__ __forceinline__ float warpSum(float v) {
#pragma unroll
    for (int o = 16; o; o >>= 1) v += __shfl_xor_sync(0xffffffffu, v, o);
    return v;
}
__device__ __forceinline__ float blockSum(float v, float* sh) {
    int lane = threadIdx.x & 31, w = threadIdx.x >> 5;
    v = warpSum(v);
    if (lane == 0) sh[w] = v;
    __syncthreads();
    if (threadIdx.x == 0) {
        int nw = (blockDim.x + 31) >> 5;
        float r = 0.f;
        for (int i = 0; i < nw; i++) r += sh[i];
        sh[0] = r;
    }
    __syncthreads();
    float r = sh[0];
    __syncthreads();
    return r;
}
__device__ __forceinline__ float ftanh(float x) {
    float y;
    asm("tanh.approx.f32 %0, %1;" : "=f"(y) : "f"(x));
    return y;
}
__device__ __forceinline__ float fsigmoid(float z) {
    return __fdividef(1.f, 1.f + __expf(-z));
}
__device__ __forceinline__ void mma_f16(float* c, const unsigned* a, const unsigned* b) {
    asm volatile(
        "mma.sync.aligned.m16n8k16.row.col.f32.f16.f16.f32 "
        "{%0,%1,%2,%3}, {%4,%5,%6,%7}, {%8,%9}, {%0,%1,%2,%3};"
        : "+f"(c[0]), "+f"(c[1]), "+f"(c[2]), "+f"(c[3])
        : "r"(a[0]), "r"(a[1]), "r"(a[2]), "r"(a[3]), "r"(b[0]), "r"(b[1]));
}
__device__ __forceinline__ unsigned smemA(const void* p) {
    return (unsigned)__cvta_generic_to_shared(p);
}
__device__ __forceinline__ float2 h2(const __half* p) {
    __half2 v = *(const __half2*)p;
    return __half22float2(v);
}
__device__ __forceinline__ void h8(const __half* p, float* f) {
    uint4 u = *(const uint4*)p;
    const __half2* h = (const __half2*)&u;
#pragma unroll
    for (int k = 0; k < 4; k++) {
        float2 t = __half22float2(h[k]);
        f[2 * k] = t.x;
        f[2 * k + 1] = t.y;
    }
}
__device__ __forceinline__ void sth8(__half* p, const float* f) {
    uint4 u;
    __half2* h = (__half2*)&u;
#pragma unroll
    for (int k = 0; k < 4; k++) h[k] = __floats2half2_rn(f[2 * k], f[2 * k + 1]);
    *(uint4*)p = u;
}
#define CP16(dst, src) asm volatile("cp.async.cg.shared.global [%0], [%1], 16;" ::"r"(dst), "l"(src))
#define CPCOMMIT() asm volatile("cp.async.commit_group;")
#define CPWAIT1() asm volatile("cp.async.wait_group 1;")
#define CPWAIT0() asm volatile("cp.async.wait_group 0;")

// ---------------- fused prep ----------------
__global__ void k_prep(const float* __restrict__ ent, const float* __restrict__ rel,
                       const float* __restrict__ Ge, const float* __restrict__ Gr) {
    int i = blockIdx.x * blockDim.x + threadIdx.x;
    if (i < NN) g_cnt[i] = 0;
    if (i < NN * FF) g_ent16[i] = __float2half_rn(ent[i]);
    if (i < RR * FF) g_rel16[i] = __float2half_rn(rel[i]);
    if (i < FDIM * FDIM) {
        int n = i / FDIM, k = i % FDIM;
        g_gate16T[0][i] = __float2half_rn(Ge[k * FDIM + n]);
        g_gate16T[1][i] = __float2half_rn(Gr[k * FDIM + n]);
    }
}

// ---------------- CSR build ----------------
__global__ void k_hist(const int* __restrict__ edst) {
    int e = blockIdx.x * blockDim.x + threadIdx.x;
    if (e < EE) atomicAdd(&g_cnt[edst[e]], 1);
}
__global__ void k_scan() {
    __shared__ int partial[1024];
    int tid = threadIdx.x;
    const int CH = 49;
    int base = tid * CH;
    int s = 0;
    for (int i = 0; i < CH; i++) {
        int idx = base + i;
        if (idx < NN) s += g_cnt[idx];
    }
    partial[tid] = s;
    __syncthreads();
    for (int off = 1; off < 1024; off <<= 1) {
        int v = (tid >= off) ? partial[tid - off] : 0;
        __syncthreads();
        partial[tid] += v;
        __syncthreads();
    }
    int run = (tid == 0) ? 0 : partial[tid - 1];
    for (int i = 0; i < CH; i++) {
        int idx = base + i;
        if (idx < NN) {
            g_ptr[idx] = run;
            g_cur[idx] = run;
            run += g_cnt[idx];
        }
    }
    if (tid == 0) g_ptr[NN] = EE;
}
__global__ void k_scatter(const int* __restrict__ esrc, const int* __restrict__ edst,
                          const int* __restrict__ erel) {
    int e = blockIdx.x * blockDim.x + threadIdx.x;
    if (e < EE) {
        int d = edst[e];
        int p = atomicAdd(&g_cur[d], 1);
        g_ssrc[p] = esrc[e];
        g_srel[p] = erel[e];
    }
}

// ---------------- per-relation: l2norm rows (fp16) + exp(score) tables ----------------
__global__ void k_relnorm(const float* __restrict__ rel_emb,
                          const float* __restrict__ attn_e,
                          const float* __restrict__ attn_r) {
    __shared__ float sh[32];
    int r = blockIdx.x, t = threadIdx.x;
    float v = rel_emb[r * FF + t];
    float s = blockSum(v * v, sh);
    float inv = 1.f / fmaxf(sqrtf(s), 1e-12f);
    float rn = v * inv;
    g_relnorm16[r * FF + t] = __float2half_rn(rn);
    float d0 = blockSum(rn * attn_e[t], sh);
    float d1 = blockSum(rn * attn_e[FF + t], sh);
    float d2 = blockSum(rn * attn_r[t], sh);
    float d3 = blockSum(rn * attn_r[FF + t], sh);
    if (t == 0) {
        g_exps[(0 * LDP + 0) * RR + r] = expf(d0);
        g_exps[(0 * LDP + 1) * RR + r] = expf(d1);
        g_exps[(1 * LDP + 0) * RR + r] = expf(d2);
        g_exps[(1 * LDP + 1) * RR + r] = expf(d3);
    }
}

// ---------------- proxy rows ----------------
__global__ void k_proxyn(const float* __restrict__ pe, const float* __restrict__ pr) {
    __shared__ float sh[32];
    int dual = blockIdx.x >> 6, p = blockIdx.x & 63, t = threadIdx.x;
    const float* src = dual ? pr : pe;
    float v = src[p * FDIM + t];
    float s = blockSum(v * v, sh);
    float inv = 1.f / fmaxf(sqrtf(s), 1e-12f);
    g_proxyn16[dual][p * FDIM + t] = __float2half_rn(v * inv);
    g_proxyT16[dual][t * PP + p] = __float2half_rn(v);
}

// ---------------- initial features: half-warp per edge + index prefetch ----------------
__global__ void k_init() {
    int warp = threadIdx.x >> 5, lane = threadIdx.x & 31;
    int n = blockIdx.x * 8 + warp;
    if (n >= NN) return;
    int half = lane >> 4, sub = lane & 15;
    int beg = g_ptr[n], end = g_ptr[n + 1];
    float ae[8] = {}, ar[8] = {};
    int i = beg + half;
    if (i < end) {
        int s = g_ssrc[i], r = g_srel[i];
        for (; i < end;) {
            int inext = i + 2;
            int sn = 0, rn_ = 0;
            bool more = inext < end;
            if (more) { sn = g_ssrc[inext]; rn_ = g_srel[inext]; }
            float a[8], b[8];
            h8(&g_ent16[(size_t)s * FF + sub * 8], a);
            h8(&g_rel16[(size_t)r * FF + sub * 8], b);
#pragma unroll
            for (int k = 0; k < 8; k++) { ae[k] += a[k]; ar[k] += b[k]; }
            i = inext; s = sn; r = rn_;
        }
    }
#pragma unroll
    for (int k = 0; k < 8; k++) {
        ae[k] += __shfl_xor_sync(0xffffffffu, ae[k], 16);
        ar[k] += __shfl_xor_sync(0xffffffffu, ar[k], 16);
    }
    float inv = 1.f / fmaxf((float)(end - beg), 1.f);
    const float* src = half ? ar : ae;
    float o[8];
#pragma unroll
    for (int k = 0; k < 8; k++) o[k] = ftanh(src[k] * inv);
    __half* dst = (half ? g_outr16 : g_oute16) + (size_t)n * FDIM + sub * 8;
    sth8(dst, o);
}

// ---------------- GNN layer: half-warp per edge (R14 structure) + index prefetch ----------------
__global__ void k_layer(int l) {
    int warp = threadIdx.x >> 5, lane = threadIdx.x & 31;
    int n = blockIdx.x * 8 + warp;
    if (n >= NN) return;
    int half = lane >> 4, sub = lane & 15;
    const float* __restrict__ exe = g_exps + (0 * LDP + l) * RR;
    const float* __restrict__ exr = g_exps + (1 * LDP + l) * RR;
    int beg = g_ptr[n], end = g_ptr[n + 1];
    int deg = end - beg;
    int iters = (deg + 1) >> 1;   // warp-uniform

    float acce[8] = {}, accr[8] = {};
    float se = 0.f, sr = 0.f;
    int co = l * FF + sub * 8;

    // prefetch iteration 0's indices
    int i = beg + half;
    bool v = i < end;
    int ec = v ? i : (end - 1);
    int s = g_ssrc[ec], r = g_srel[ec];

    for (int it = 0; it < iters; it++) {
        // prefetch next iteration's indices before the heavy gathers
        int inext = beg + 2 * (it + 1) + half;
        bool vn = inext < end;
        int ecn = vn ? inext : (end - 1);
        int sn = 0, rnn = 0;
        if (it + 1 < iters) { sn = g_ssrc[ecn]; rnn = g_srel[ecn]; }

        float rn[8], fe[8], fr[8];
        h8(&g_relnorm16[r * FF + sub * 8], rn);
        h8(&g_oute16[(size_t)s * FDIM + co], fe);
        h8(&g_outr16[(size_t)s * FDIM + co], fr);
        float de = 0.f, dr = 0.f;
#pragma unroll
        for (int k = 0; k < 8; k++) { de += fe[k] * rn[k]; dr += fr[k] * rn[k]; }
#pragma unroll
        for (int o = 1; o < 16; o <<= 1) {
            de += __shfl_xor_sync(0xffffffffu, de, o);
            dr += __shfl_xor_sync(0xffffffffu, dr, o);
        }
        float we = v ? exe[r] : 0.f;
        float wr = v ? exr[r] : 0.f;
        se += we; sr += wr;
        float ce = -2.f * de, cr = -2.f * dr;
#pragma unroll
        for (int k = 0; k < 8; k++) {
            acce[k] += we * fmaf(ce, rn[k], fe[k]);
            accr[k] += wr * fmaf(cr, rn[k], fr[k]);
        }
        v = vn; s = sn; r = rnn;
    }
    // fold the two halves
#pragma unroll
    for (int k = 0; k < 8; k++) {
        acce[k] += __shfl_xor_sync(0xffffffffu, acce[k], 16);
        accr[k] += __shfl_xor_sync(0xffffffffu, accr[k], 16);
    }
    se += __shfl_xor_sync(0xffffffffu, se, 16);
    sr += __shfl_xor_sync(0xffffffffu, sr, 16);
    float ise = (se > 0.f) ? 1.f / se : 0.f;
    float isr = (sr > 0.f) ? 1.f / sr : 0.f;
    int off = (l + 1) * FF + sub * 8;
    float o[8];
    if (half == 0) {
#pragma unroll
        for (int k = 0; k < 8; k++) o[k] = ftanh(acce[k] * ise);
        sth8(&g_oute16[(size_t)n * FDIM + off], o);
    } else {
#pragma unroll
        for (int k = 0; k < 8; k++) o[k] = ftanh(accr[k] * isr);
        sth8(&g_outr16[(size_t)n * FDIM + off], o);
    }
}

// ================= fused GEMM1+GEMM2: attw stays in smem =================
#define G12_SMEM 64512

__global__ __launch_bounds__(256) void k_gemm12() {
    extern __shared__ __align__(16) char dsm[];
    __half(*As)[128][40] = (__half(*)[128][40])(dsm);
    __half(*Bs)[64][40] = (__half(*)[64][40])(dsm + 20480);
    __half(*attwS)[72] = (__half(*)[72])(dsm);
    float(*Ls)[66] = (float(*)[66])(dsm + 30720);
    __half(*BsP)[72] = (__half(*)[72])(dsm + 30720);

    int dual = blockIdx.z;
    int mb = blockIdx.x * 128;
    const __half* X16 = dual ? g_outr16 : g_oute16;
    const __half* Pn = g_proxyn16[dual];
    const __half* PT = g_proxyT16[dual];
    __half* pf16 = g_pf16 + (size_t)dual * NN * FDIM;
    int tid = threadIdx.x, lane = tid & 31, wid = tid >> 5;
    int g = lane >> 2, t4 = lane & 3;

    // ---- phase A: logits = invn*(X16 @ Pn^T), softmax -> attwS ----
    {
        int warpM = wid * 16;
        auto loadTiles = [&](int buf, int kc) {
#pragma unroll
            for (int i = 0; i < 2; i++) {
                int id = tid + i * 256;
                int row = id >> 2, cq = (id & 3) * 8;
                int gr = min(mb + row, NN - 1);
                CP16(smemA(&As[buf][row][cq]), &X16[(size_t)gr * FDIM + kc + cq]);
            }
            {
                int row = tid >> 2, cq = (tid & 3) * 8;
                CP16(smemA(&Bs[buf][row][cq]), &Pn[(size_t)row * FDIM + kc + cq]);
            }
            CPCOMMIT();
        };

        float acc[8][4] = {};
        float sq0 = 0.f, sq1 = 0.f;
        loadTiles(0, 0);
        const int NT = FDIM / 32;
        for (int t = 0; t < NT; t++) {
            int buf = t & 1;
            if (t + 1 < NT) { loadTiles(buf ^ 1, (t + 1) * 32); CPWAIT1(); }
            else CPWAIT0();
            __syncthreads();
#pragma unroll
            for (int ks = 0; ks < 2; ks++) {
                int k0 = ks * 16;
                unsigned a[4], b[8][2];
                a[0] = *(const unsigned*)&As[buf][warpM + g][k0 + 2 * t4];
                a[1] = *(const unsigned*)&As[buf][warpM + g + 8][k0 + 2 * t4];
                a[2] = *(const unsigned*)&As[buf][warpM + g][k0 + 2 * t4 + 8];
                a[3] = *(const unsigned*)&As[buf][warpM + g + 8][k0 + 2 * t4 + 8];
                {
                    float2 f0 = __half22float2(*(const __half2*)&a[0]);
                    float2 f1 = __half22float2(*(const __half2*)&a[1]);
                    float2 f2 = __half22float2(*(const __half2*)&a[2]);
                    float2 f3 = __half22float2(*(const __half2*)&a[3]);
                    sq0 += f0.x * f0.x + f0.y * f0.y + f2.x * f2.x + f2.y * f2.y;
                    sq1 += f1.x * f1.x + f1.y * f1.y + f3.x * f3.x + f3.y * f3.y;
                }
#pragma unroll
                for (int nt = 0; nt < 8; nt++) {
                    b[nt][0] = *(const unsigned*)&Bs[buf][nt * 8 + g][k0 + 2 * t4];
                    b[nt][1] = *(const unsigned*)&Bs[buf][nt * 8 + g][k0 + 2 * t4 + 8];
                }
#pragma unroll
                for (int nt = 0; nt < 8; nt++) mma_f16(acc[nt], a, b[nt]);
            }
            __syncthreads();
        }
#pragma unroll
        for (int o = 1; o < 4; o <<= 1) {
            sq0 += __shfl_xor_sync(0xffffffffu, sq0, o);
            sq1 += __shfl_xor_sync(0xffffffffu, sq1, o);
        }
        float i0 = 1.f / fmaxf(sqrtf(sq0), 1e-12f);
        float i1 = 1.f / fmaxf(sqrtf(sq1), 1e-12f);
#pragma unroll
        for (int nt = 0; nt < 8; nt++) {
            int r0 = warpM + g, r1 = warpM + g + 8, c0 = nt * 8 + t4 * 2;
            Ls[r0][c0] = acc[nt][0] * i0; Ls[r0][c0 + 1] = acc[nt][1] * i0;
            Ls[r1][c0] = acc[nt][2] * i1; Ls[r1][c0 + 1] = acc[nt][3] * i1;
        }
        __syncthreads();
        if (tid < 128) {
            float m = -3e38f;
            for (int c = 0; c < PP; c++) m = fmaxf(m, Ls[tid][c]);
            float s = 0.f;
            for (int c = 0; c < PP; c++) s += __expf(Ls[tid][c] - m);
            float is = __fdividef(1.f, s);
            for (int c = 0; c < PP; c++)
                attwS[tid][c] = __float2half_rn(__expf(Ls[tid][c] - m) * is);
        }
        __syncthreads();
    }

    // ---- phase B: pf16 = X16 - attwS @ proxy ----
    {
        int warpM = (wid & 3) * 32, warpN = (wid >> 2) * 64;
        for (int nc = 0; nc < 3; nc++) {
#pragma unroll
            for (int i = 0; i < 4; i++) {
                int id = tid + i * 256;
                int row = id >> 3, cq = (id & 7) * 8;
                CP16(smemA(&BsP[row][cq]), &PT[(size_t)(nc * 128 + row) * PP + cq]);
            }
            CPCOMMIT();
            CPWAIT0();
            __syncthreads();
            float acc[2][8][4] = {};
#pragma unroll
            for (int ks = 0; ks < 4; ks++) {
                int k0 = ks * 16;
                unsigned a[2][4], b[8][2];
#pragma unroll
                for (int mt = 0; mt < 2; mt++) {
                    int r = warpM + mt * 16;
                    a[mt][0] = *(const unsigned*)&attwS[r + g][k0 + 2 * t4];
                    a[mt][1] = *(const unsigned*)&attwS[r + g + 8][k0 + 2 * t4];
                    a[mt][2] = *(const unsigned*)&attwS[r + g][k0 + 2 * t4 + 8];
                    a[mt][3] = *(const unsigned*)&attwS[r + g + 8][k0 + 2 * t4 + 8];
                }
#pragma unroll
                for (int nt = 0; nt < 8; nt++) {
                    b[nt][0] = *(const unsigned*)&BsP[warpN + nt * 8 + g][k0 + 2 * t4];
                    b[nt][1] = *(const unsigned*)&BsP[warpN + nt * 8 + g][k0 + 2 * t4 + 8];
                }
#pragma unroll
                for (int mt = 0; mt < 2; mt++)
#pragma unroll
                    for (int nt = 0; nt < 8; nt++) mma_f16(acc[mt][nt], a[mt], b[nt]);
            }
#pragma unroll
            for (int mt = 0; mt < 2; mt++) {
#pragma unroll
                for (int nt = 0; nt < 8; nt++) {
                    int col = nc * 128 + warpN + nt * 8 + t4 * 2;
                    int r0 = mb + warpM + mt * 16 + g, r1 = r0 + 8;
                    if (r0 < NN) {
                        float2 x = h2(&X16[(size_t)r0 * FDIM + col]);
                        *(__half2*)&pf16[(size_t)r0 * FDIM + col] =
                            __floats2half2_rn(x.x - acc[mt][nt][0], x.y - acc[mt][nt][1]);
                    }
                    if (r1 < NN) {
                        float2 x = h2(&X16[(size_t)r1 * FDIM + col]);
                        *(__half2*)&pf16[(size_t)r1 * FDIM + col] =
                            __floats2half2_rn(x.x - acc[mt][nt][2], x.y - acc[mt][nt][3]);
                    }
                }
            }
            __syncthreads();
        }
    }
}

// GEMM3: gate = sigmoid(pf16@G + b); out = gate*X16 + (1-gate)*pf16.
__global__ __launch_bounds__(256) void k_gemm3t(const float* __restrict__ bias_e,
                                                const float* __restrict__ bias_r,
                                                float* __restrict__ out) {
    __shared__ __half As[2][128][40];
    __shared__ __half Bs[2][128][40];
    int dual = blockIdx.z;
    int mb = blockIdx.x * 128, nb = blockIdx.y * 128;
    const __half* X16 = dual ? g_outr16 : g_oute16;
    const __half* GT = g_gate16T[dual];
    const float* bias = dual ? bias_r : bias_e;
    const __half* pf16 = g_pf16 + (size_t)dual * NN * FDIM;
    int tid = threadIdx.x, lane = tid & 31, wid = tid >> 5;
    int g = lane >> 2, t4 = lane & 3;
    int warpM = (wid & 3) * 32, warpN = (wid >> 2) * 64;

    auto loadTiles = [&](int buf, int kc) {
#pragma unroll
        for (int i = 0; i < 2; i++) {
            int id = tid + i * 256;
            int row = id >> 2, cq = (id & 3) * 8;
            int gr = min(mb + row, NN - 1);
            CP16(smemA(&As[buf][row][cq]), &pf16[(size_t)gr * FDIM + kc + cq]);
        }
#pragma unroll
        for (int i = 0; i < 2; i++) {
            int id = tid + i * 256;
            int row = id >> 2, cq = (id & 3) * 8;
            CP16(smemA(&Bs[buf][row][cq]), &GT[(size_t)(nb + row) * FDIM + kc + cq]);
        }
        CPCOMMIT();
    };

    float acc[2][8][4] = {};
    loadTiles(0, 0);
    const int NT = FDIM / 32;
    for (int t = 0; t < NT; t++) {
        int buf = t & 1;
        if (t + 1 < NT) { loadTiles(buf ^ 1, (t + 1) * 32); CPWAIT1(); }
        else CPWAIT0();
        __syncthreads();
#pragma unroll
        for (int ks = 0; ks < 2; ks++) {
            int k0 = ks * 16;
            unsigned a[2][4], b[8][2];
#pragma unroll
            for (int mt = 0; mt < 2; mt++) {
                int r = warpM + mt * 16;
                a[mt][0] = *(const unsigned*)&As[buf][r + g][k0 + 2 * t4];
                a[mt][1] = *(const unsigned*)&As[buf][r + g + 8][k0 + 2 * t4];
                a[mt][2] = *(const unsigned*)&As[buf][r + g][k0 + 2 * t4 + 8];
                a[mt][3] = *(const unsigned*)&As[buf][r + g + 8][k0 + 2 * t4 + 8];
            }
#pragma unroll
            for (int nt = 0; nt < 8; nt++) {
                b[nt][0] = *(const unsigned*)&Bs[buf][warpN + nt * 8 + g][k0 + 2 * t4];
                b[nt][1] = *(const unsigned*)&Bs[buf][warpN + nt * 8 + g][k0 + 2 * t4 + 8];
            }
#pragma unroll
            for (int mt = 0; mt < 2; mt++)
#pragma unroll
                for (int nt = 0; nt < 8; nt++) mma_f16(acc[mt][nt], a[mt], b[nt]);
        }
        __syncthreads();
    }
#pragma unroll
    for (int mt = 0; mt < 2; mt++) {
#pragma unroll
        for (int nt = 0; nt < 8; nt++) {
            int col = nb + warpN + nt * 8 + t4 * 2;
            float b0 = bias[col], b1 = bias[col + 1];
            int r0 = mb + warpM + mt * 16 + g, r1 = r0 + 8;
            if (r0 < NN) {
                float g0 = fsigmoid(acc[mt][nt][0] + b0);
                float g1 = fsigmoid(acc[mt][nt][1] + b1);
                float2 x = h2(&X16[(size_t)r0 * FDIM + col]);
                float2 p = h2(&pf16[(size_t)r0 * FDIM + col]);
                float2 o = {g0 * x.x + (1.f - g0) * p.x, g1 * x.y + (1.f - g1) * p.y};
                *(float2*)&out[(size_t)r0 * (2 * FDIM) + dual * FDIM + col] = o;
            }
            if (r1 < NN) {
                float g0 = fsigmoid(acc[mt][nt][2] + b0);
                float g1 = fsigmoid(acc[mt][nt][3] + b1);
                float2 x = h2(&X16[(size_t)r1 * FDIM + col]);
                float2 p = h2(&pf16[(size_t)r1 * FDIM + col]);
                float2 o = {g0 * x.x + (1.f - g0) * p.x, g1 * x.y + (1.f - g1) * p.y};
                *(float2*)&out[(size_t)r1 * (2 * FDIM) + dual * FDIM + col] = o;
            }
        }
    }
}

// ---------------- launch ----------------
extern "C" void kernel_launch(void* const* d_in, const int* in_sizes, int n_in,
                              void* d_out, int out_size) {
    const float* ent     = (const float*)d_in[0];
    const float* rel     = (const float*)d_in[1];
    const int*   esrc    = (const int*)d_in[2];
    const int*   edst    = (const int*)d_in[3];
    const int*   erel    = (const int*)d_in[4];
    const float* attn_e  = (const float*)d_in[5];
    const float* gate_e  = (const float*)d_in[6];
    const float* proxy_e = (const float*)d_in[7];
    const float* bias_e  = (const float*)d_in[8];
    const float* attn_r  = (const float*)d_in[9];
    const float* gate_r  = (const float*)d_in[10];
    const float* proxy_r = (const float*)d_in[11];
    const float* bias_r  = (const float*)d_in[12];
    float* out = (float*)d_out;

    cudaFuncSetAttribute(k_gemm12, cudaFuncAttributeMaxDynamicSharedMemorySize, G12_SMEM);

    k_prep<<<25000, 256>>>(ent, rel, gate_e, gate_r);
    k_hist<<<3125, 256>>>(edst);
    k_scan<<<1, 1024>>>();
    k_scatter<<<3125, 256>>>(esrc, edst, erel);
    k_relnorm<<<RR, FF>>>(rel, attn_e, attn_r);
    k_init<<<6250, 256>>>();
    k_layer<<<6250, 256>>>(0);
    k_layer<<<6250, 256>>>(1);
    k_proxyn<<<128, FDIM>>>(proxy_e, proxy_r);
    k_gemm12<<<dim3(391, 1, 2), 256, G12_SMEM>>>();
    k_gemm3t<<<dim3(391, 3, 2), 256>>>(bias_e, bias_r, out);
}

// round 17
// speedup vs baseline: 1.0839x; 1.0260x over previous
#include <cuda_runtime.h>
#include <cuda_fp16.h>
#include <math.h>

#define NN 50000
#define EE 800000
#define RR 2000
#define FF 128
#define LDP 2
#define FDIM 384
#define PP 64

// ---------------- scratch ----------------
__device__ int    g_cnt[NN];
__device__ int    g_ptr[NN + 1];
__device__ int    g_cur[NN];
__device__ int2   g_sedge[EE];                    // packed (src, rel)
__device__ __half g_ent16[(size_t)NN * FF];
__device__ __half g_rel16[RR * FF];
__device__ __half g_relnorm16[RR * FF];
__device__ float  g_exps[2 * LDP * RR];
__device__ __half g_oute16[(size_t)NN * FDIM];
__device__ __half g_outr16[(size_t)NN * FDIM];
__device__ __half g_proxyn16[2][PP * FDIM];
__device__ __half g_proxyT16[2][FDIM * PP];
__device__ __half g_gate16T[2][FDIM * FDIM];
__device__ __half g_pf16[(size_t)2 * NN * FDIM];

// ---------------- helpers ----------------
__device__ __forceinline__ float warpSum(float v) {
#pragma unroll
    for (int o = 16; o; o >>= 1) v += __shfl_xor_sync(0xffffffffu, v, o);
    return v;
}
__device__ __forceinline__ float blockSum(float v, float* sh) {
    int lane = threadIdx.x & 31, w = threadIdx.x >> 5;
    v = warpSum(v);
    if (lane == 0) sh[w] = v;
    __syncthreads();
    if (threadIdx.x == 0) {
        int nw = (blockDim.x + 31) >> 5;
        float r = 0.f;
        for (int i = 0; i < nw; i++) r += sh[i];
        sh[0] = r;
    }
    __syncthreads();
    float r = sh[0];
    __syncthreads();
    return r;
}
__device__ __forceinline__ float ftanh(float x) {
    float y;
    asm("tanh.approx.f32 %0, %1;" : "=f"(y) : "f"(x));
    return y;
}
__device__ __forceinline__ float fsigmoid(float z) {
    return __fdividef(1.f, 1.f + __expf(-z));
}
__device__ __forceinline__ void mma_f16(float* c, const unsigned* a, const unsigned* b) {
    asm volatile(
        "mma.sync.aligned.m16n8k16.row.col.f32.f16.f16.f32 "
        "{%0,%1,%2,%3}, {%4,%5,%6,%7}, {%8,%9}, {%0,%1,%2,%3};"
        : "+f"(c[0]), "+f"(c[1]), "+f"(c[2]), "+f"(c[3])
        : "r"(a[0]), "r"(a[1]), "r"(a[2]), "r"(a[3]), "r"(b[0]), "r"(b[1]));
}
__device__ __forceinline__ unsigned smemA(const void* p) {
    return (unsigned)__cvta_generic_to_shared(p);
}
__device__ __forceinline__ float2 h2(const __half* p) {
    __half2 v = *(const __half2*)p;
    return __half22float2(v);
}
__device__ __forceinline__ void h8(const __half* p, float* f) {
    uint4 u = *(const uint4*)p;
    const __half2* h = (const __half2*)&u;
#pragma unroll
    for (int k = 0; k < 4; k++) {
        float2 t = __half22float2(h[k]);
        f[2 * k] = t.x;
        f[2 * k + 1] = t.y;
    }
}
__device__ __forceinline__ void sth8(__half* p, const float* f) {
    uint4 u;
    __half2* h = (__half2*)&u;
#pragma unroll
    for (int k = 0; k < 4; k++) h[k] = __floats2half2_rn(f[2 * k], f[2 * k + 1]);
    *(uint4*)p = u;
}
#define CP16(dst, src) asm volatile("cp.async.cg.shared.global [%0], [%1], 16;" ::"r"(dst), "l"(src))
#define CPCOMMIT() asm volatile("cp.async.commit_group;")
#define CPWAIT1() asm volatile("cp.async.wait_group 1;")
#define CPWAIT0() asm volatile("cp.async.wait_group 0;")

// ---------------- fused prep ----------------
__global__ void k_prep(const float* __restrict__ ent, const float* __restrict__ rel,
                       const float* __restrict__ Ge, const float* __restrict__ Gr) {
    int i = blockIdx.x * blockDim.x + threadIdx.x;
    if (i < NN) g_cnt[i] = 0;
    if (i < NN * FF) g_ent16[i] = __float2half_rn(ent[i]);
    if (i < RR * FF) g_rel16[i] = __float2half_rn(rel[i]);
    if (i < FDIM * FDIM) {
        int n = i / FDIM, k = i % FDIM;
        g_gate16T[0][i] = __float2half_rn(Ge[k * FDIM + n]);
        g_gate16T[1][i] = __float2half_rn(Gr[k * FDIM + n]);
    }
}

// ---------------- CSR build ----------------
__global__ void k_hist(const int* __restrict__ edst) {
    int e = blockIdx.x * blockDim.x + threadIdx.x;
    if (e < EE) atomicAdd(&g_cnt[edst[e]], 1);
}
__global__ void k_scan() {
    __shared__ int partial[1024];
    int tid = threadIdx.x;
    const int CH = 49;
    int base = tid * CH;
    int s = 0;
    for (int i = 0; i < CH; i++) {
        int idx = base + i;
        if (idx < NN) s += g_cnt[idx];
    }
    partial[tid] = s;
    __syncthreads();
    for (int off = 1; off < 1024; off <<= 1) {
        int v = (tid >= off) ? partial[tid - off] : 0;
        __syncthreads();
        partial[tid] += v;
        __syncthreads();
    }
    int run = (tid == 0) ? 0 : partial[tid - 1];
    for (int i = 0; i < CH; i++) {
        int idx = base + i;
        if (idx < NN) {
            g_ptr[idx] = run;
            g_cur[idx] = run;
            run += g_cnt[idx];
        }
    }
    if (tid == 0) g_ptr[NN] = EE;
}
__global__ void k_scatter(const int* __restrict__ esrc, const int* __restrict__ edst,
                          const int* __restrict__ erel) {
    int e = blockIdx.x * blockDim.x + threadIdx.x;
    if (e < EE) {
        int d = edst[e];
        int p = atomicAdd(&g_cur[d], 1);
        g_sedge[p] = make_int2(esrc[e], erel[e]);
    }
}

// ---------------- per-relation: l2norm rows (fp16) + exp(score) tables ----------------
__global__ void k_relnorm(const float* __restrict__ rel_emb,
                          const float* __restrict__ attn_e,
                          const float* __restrict__ attn_r) {
    __shared__ float sh[32];
    int r = blockIdx.x, t = threadIdx.x;
    float v = rel_emb[r * FF + t];
    float s = blockSum(v * v, sh);
    float inv = 1.f / fmaxf(sqrtf(s), 1e-12f);
    float rn = v * inv;
    g_relnorm16[r * FF + t] = __float2half_rn(rn);
    float d0 = blockSum(rn * attn_e[t], sh);
    float d1 = blockSum(rn * attn_e[FF + t], sh);
    float d2 = blockSum(rn * attn_r[t], sh);
    float d3 = blockSum(rn * attn_r[FF + t], sh);
    if (t == 0) {
        g_exps[(0 * LDP + 0) * RR + r] = expf(d0);
        g_exps[(0 * LDP + 1) * RR + r] = expf(d1);
        g_exps[(1 * LDP + 0) * RR + r] = expf(d2);
        g_exps[(1 * LDP + 1) * RR + r] = expf(d3);
    }
}

// ---------------- proxy rows ----------------
__global__ void k_proxyn(const float* __restrict__ pe, const float* __restrict__ pr) {
    __shared__ float sh[32];
    int dual = blockIdx.x >> 6, p = blockIdx.x & 63, t = threadIdx.x;
    const float* src = dual ? pr : pe;
    float v = src[p * FDIM + t];
    float s = blockSum(v * v, sh);
    float inv = 1.f / fmaxf(sqrtf(s), 1e-12f);
    g_proxyn16[dual][p * FDIM + t] = __float2half_rn(v * inv);
    g_proxyT16[dual][t * PP + p] = __float2half_rn(v);
}

// ---------------- initial features: half-warp per edge (R14) + packed indices ----------------
__global__ void k_init() {
    int warp = threadIdx.x >> 5, lane = threadIdx.x & 31;
    int n = blockIdx.x * 8 + warp;
    if (n >= NN) return;
    int half = lane >> 4, sub = lane & 15;
    int beg = g_ptr[n], end = g_ptr[n + 1];
    float ae[8] = {}, ar[8] = {};
    for (int i = beg + half; i < end; i += 2) {
        int2 e = g_sedge[i];
        float a[8], b[8];
        h8(&g_ent16[(size_t)e.x * FF + sub * 8], a);
        h8(&g_rel16[(size_t)e.y * FF + sub * 8], b);
#pragma unroll
        for (int k = 0; k < 8; k++) { ae[k] += a[k]; ar[k] += b[k]; }
    }
#pragma unroll
    for (int k = 0; k < 8; k++) {
        ae[k] += __shfl_xor_sync(0xffffffffu, ae[k], 16);
        ar[k] += __shfl_xor_sync(0xffffffffu, ar[k], 16);
    }
    float inv = 1.f / fmaxf((float)(end - beg), 1.f);
    const float* src = half ? ar : ae;
    float o[8];
#pragma unroll
    for (int k = 0; k < 8; k++) o[k] = ftanh(src[k] * inv);
    __half* dst = (half ? g_outr16 : g_oute16) + (size_t)n * FDIM + sub * 8;
    sth8(dst, o);
}

// ---------------- GNN layer: half-warp per edge (R14) + packed indices ----------------
__global__ void k_layer(int l) {
    int warp = threadIdx.x >> 5, lane = threadIdx.x & 31;
    int n = blockIdx.x * 8 + warp;
    if (n >= NN) return;
    int half = lane >> 4, sub = lane & 15;
    const float* __restrict__ exe = g_exps + (0 * LDP + l) * RR;
    const float* __restrict__ exr = g_exps + (1 * LDP + l) * RR;
    int beg = g_ptr[n], end = g_ptr[n + 1];
    int deg = end - beg;
    int iters = (deg + 1) >> 1;   // warp-uniform

    float acce[8] = {}, accr[8] = {};
    float se = 0.f, sr = 0.f;
    int co = l * FF + sub * 8;
    for (int it = 0; it < iters; it++) {
        int i = beg + 2 * it + half;
        bool v = i < end;
        int ec = v ? i : (end - 1);
        int2 e = g_sedge[ec];
        int s = e.x, r = e.y;
        float rn[8], fe[8], fr[8];
        h8(&g_relnorm16[r * FF + sub * 8], rn);
        h8(&g_oute16[(size_t)s * FDIM + co], fe);
        h8(&g_outr16[(size_t)s * FDIM + co], fr);
        float de = 0.f, dr = 0.f;
#pragma unroll
        for (int k = 0; k < 8; k++) { de += fe[k] * rn[k]; dr += fr[k] * rn[k]; }
#pragma unroll
        for (int o = 1; o < 16; o <<= 1) {
            de += __shfl_xor_sync(0xffffffffu, de, o);
            dr += __shfl_xor_sync(0xffffffffu, dr, o);
        }
        float we = v ? exe[r] : 0.f;
        float wr = v ? exr[r] : 0.f;
        se += we; sr += wr;
        float ce = -2.f * de, cr = -2.f * dr;
#pragma unroll
        for (int k = 0; k < 8; k++) {
            acce[k] += we * fmaf(ce, rn[k], fe[k]);
            accr[k] += wr * fmaf(cr, rn[k], fr[k]);
        }
    }
    // fold the two halves
#pragma unroll
    for (int k = 0; k < 8; k++) {
        acce[k] += __shfl_xor_sync(0xffffffffu, acce[k], 16);
        accr[k] += __shfl_xor_sync(0xffffffffu, accr[k], 16);
    }
    se += __shfl_xor_sync(0xffffffffu, se, 16);
    sr += __shfl_xor_sync(0xffffffffu, sr, 16);
    float ise = (se > 0.f) ? 1.f / se : 0.f;
    float isr = (sr > 0.f) ? 1.f / sr : 0.f;
    int off = (l + 1) * FF + sub * 8;
    float o[8];
    if (half == 0) {
#pragma unroll
        for (int k = 0; k < 8; k++) o[k] = ftanh(acce[k] * ise);
        sth8(&g_oute16[(size_t)n * FDIM + off], o);
    } else {
#pragma unroll
        for (int k = 0; k < 8; k++) o[k] = ftanh(accr[k] * isr);
        sth8(&g_outr16[(size_t)n * FDIM + off], o);
    }
}

// ================= fused GEMM1+GEMM2: attw stays in smem =================
#define G12_SMEM 64512

__global__ __launch_bounds__(256) void k_gemm12() {
    extern __shared__ __align__(16) char dsm[];
    __half(*As)[128][40] = (__half(*)[128][40])(dsm);
    __half(*Bs)[64][40] = (__half(*)[64][40])(dsm + 20480);
    __half(*attwS)[72] = (__half(*)[72])(dsm);
    float(*Ls)[66] = (float(*)[66])(dsm + 30720);
    __half(*BsP)[72] = (__half(*)[72])(dsm + 30720);

    int dual = blockIdx.z;
    int mb = blockIdx.x * 128;
    const __half* X16 = dual ? g_outr16 : g_oute16;
    const __half* Pn = g_proxyn16[dual];
    const __half* PT = g_proxyT16[dual];
    __half* pf16 = g_pf16 + (size_t)dual * NN * FDIM;
    int tid = threadIdx.x, lane = tid & 31, wid = tid >> 5;
    int g = lane >> 2, t4 = lane & 3;

    // ---- phase A: logits = invn*(X16 @ Pn^T), softmax -> attwS ----
    {
        int warpM = wid * 16;
        auto loadTiles = [&](int buf, int kc) {
#pragma unroll
            for (int i = 0; i < 2; i++) {
                int id = tid + i * 256;
                int row = id >> 2, cq = (id & 3) * 8;
                int gr = min(mb + row, NN - 1);
                CP16(smemA(&As[buf][row][cq]), &X16[(size_t)gr * FDIM + kc + cq]);
            }
            {
                int row = tid >> 2, cq = (tid & 3) * 8;
                CP16(smemA(&Bs[buf][row][cq]), &Pn[(size_t)row * FDIM + kc + cq]);
            }
            CPCOMMIT();
        };

        float acc[8][4] = {};
        float sq0 = 0.f, sq1 = 0.f;
        loadTiles(0, 0);
        const int NT = FDIM / 32;
        for (int t = 0; t < NT; t++) {
            int buf = t & 1;
            if (t + 1 < NT) { loadTiles(buf ^ 1, (t + 1) * 32); CPWAIT1(); }
            else CPWAIT0();
            __syncthreads();
#pragma unroll
            for (int ks = 0; ks < 2; ks++) {
                int k0 = ks * 16;
                unsigned a[4], b[8][2];
                a[0] = *(const unsigned*)&As[buf][warpM + g][k0 + 2 * t4];
                a[1] = *(const unsigned*)&As[buf][warpM + g + 8][k0 + 2 * t4];
                a[2] = *(const unsigned*)&As[buf][warpM + g][k0 + 2 * t4 + 8];
                a[3] = *(const unsigned*)&As[buf][warpM + g + 8][k0 + 2 * t4 + 8];
                {
                    float2 f0 = __half22float2(*(const __half2*)&a[0]);
                    float2 f1 = __half22float2(*(const __half2*)&a[1]);
                    float2 f2 = __half22float2(*(const __half2*)&a[2]);
                    float2 f3 = __half22float2(*(const __half2*)&a[3]);
                    sq0 += f0.x * f0.x + f0.y * f0.y + f2.x * f2.x + f2.y * f2.y;
                    sq1 += f1.x * f1.x + f1.y * f1.y + f3.x * f3.x + f3.y * f3.y;
                }
#pragma unroll
                for (int nt = 0; nt < 8; nt++) {
                    b[nt][0] = *(const unsigned*)&Bs[buf][nt * 8 + g][k0 + 2 * t4];
                    b[nt][1] = *(const unsigned*)&Bs[buf][nt * 8 + g][k0 + 2 * t4 + 8];
                }
#pragma unroll
                for (int nt = 0; nt < 8; nt++) mma_f16(acc[nt], a, b[nt]);
            }
            __syncthreads();
        }
#pragma unroll
        for (int o = 1; o < 4; o <<= 1) {
            sq0 += __shfl_xor_sync(0xffffffffu, sq0, o);
            sq1 += __shfl_xor_sync(0xffffffffu, sq1, o);
        }
        float i0 = 1.f / fmaxf(sqrtf(sq0), 1e-12f);
        float i1 = 1.f / fmaxf(sqrtf(sq1), 1e-12f);
#pragma unroll
        for (int nt = 0; nt < 8; nt++) {
            int r0 = warpM + g, r1 = warpM + g + 8, c0 = nt * 8 + t4 * 2;
            Ls[r0][c0] = acc[nt][0] * i0; Ls[r0][c0 + 1] = acc[nt][1] * i0;
            Ls[r1][c0] = acc[nt][2] * i1; Ls[r1][c0 + 1] = acc[nt][3] * i1;
        }
        __syncthreads();
        if (tid < 128) {
            float m = -3e38f;
            for (int c = 0; c < PP; c++) m = fmaxf(m, Ls[tid][c]);
            float s = 0.f;
            for (int c = 0; c < PP; c++) s += __expf(Ls[tid][c] - m);
            float is = __fdividef(1.f, s);
            for (int c = 0; c < PP; c++)
                attwS[tid][c] = __float2half_rn(__expf(Ls[tid][c] - m) * is);
        }
        __syncthreads();
    }

    // ---- phase B: pf16 = X16 - attwS @ proxy ----
    {
        int warpM = (wid & 3) * 32, warpN = (wid >> 2) * 64;
        for (int nc = 0; nc < 3; nc++) {
#pragma unroll
            for (int i = 0; i < 4; i++) {
                int id = tid + i * 256;
                int row = id >> 3, cq = (id & 7) * 8;
                CP16(smemA(&BsP[row][cq]), &PT[(size_t)(nc * 128 + row) * PP + cq]);
            }
            CPCOMMIT();
            CPWAIT0();
            __syncthreads();
            float acc[2][8][4] = {};
#pragma unroll
            for (int ks = 0; ks < 4; ks++) {
                int k0 = ks * 16;
                unsigned a[2][4], b[8][2];
#pragma unroll
                for (int mt = 0; mt < 2; mt++) {
                    int r = warpM + mt * 16;
                    a[mt][0] = *(const unsigned*)&attwS[r + g][k0 + 2 * t4];
                    a[mt][1] = *(const unsigned*)&attwS[r + g + 8][k0 + 2 * t4];
                    a[mt][2] = *(const unsigned*)&attwS[r + g][k0 + 2 * t4 + 8];
                    a[mt][3] = *(const unsigned*)&attwS[r + g + 8][k0 + 2 * t4 + 8];
                }
#pragma unroll
                for (int nt = 0; nt < 8; nt++) {
                    b[nt][0] = *(const unsigned*)&BsP[warpN + nt * 8 + g][k0 + 2 * t4];
                    b[nt][1] = *(const unsigned*)&BsP[warpN + nt * 8 + g][k0 + 2 * t4 + 8];
                }
#pragma unroll
                for (int mt = 0; mt < 2; mt++)
#pragma unroll
                    for (int nt = 0; nt < 8; nt++) mma_f16(acc[mt][nt], a[mt], b[nt]);
            }
#pragma unroll
            for (int mt = 0; mt < 2; mt++) {
#pragma unroll
                for (int nt = 0; nt < 8; nt++) {
                    int col = nc * 128 + warpN + nt * 8 + t4 * 2;
                    int r0 = mb + warpM + mt * 16 + g, r1 = r0 + 8;
                    if (r0 < NN) {
                        float2 x = h2(&X16[(size_t)r0 * FDIM + col]);
                        *(__half2*)&pf16[(size_t)r0 * FDIM + col] =
                            __floats2half2_rn(x.x - acc[mt][nt][0], x.y - acc[mt][nt][1]);
                    }
                    if (r1 < NN) {
                        float2 x = h2(&X16[(size_t)r1 * FDIM + col]);
                        *(__half2*)&pf16[(size_t)r1 * FDIM + col] =
                            __floats2half2_rn(x.x - acc[mt][nt][2], x.y - acc[mt][nt][3]);
                    }
                }
            }
            __syncthreads();
        }
    }
}

// GEMM3: gate = sigmoid(pf16@G + b); out = gate*X16 + (1-gate)*pf16.
__global__ __launch_bounds__(256) void k_gemm3t(const float* __restrict__ bias_e,
                                                const float* __restrict__ bias_r,
                                                float* __restrict__ out) {
    __shared__ __half As[2][128][40];
    __shared__ __half Bs[2][128][40];
    int dual = blockIdx.z;
    int mb = blockIdx.x * 128, nb = blockIdx.y * 128;
    const __half* X16 = dual ? g_outr16 : g_oute16;
    const __half* GT = g_gate16T[dual];
    const float* bias = dual ? bias_r : bias_e;
    const __half* pf16 = g_pf16 + (size_t)dual * NN * FDIM;
    int tid = threadIdx.x, lane = tid & 31, wid = tid >> 5;
    int g = lane >> 2, t4 = lane & 3;
    int warpM = (wid & 3) * 32, warpN = (wid >> 2) * 64;

    auto loadTiles = [&](int buf, int kc) {
#pragma unroll
        for (int i = 0; i < 2; i++) {
            int id = tid + i * 256;
            int row = id >> 2, cq = (id & 3) * 8;
            int gr = min(mb + row, NN - 1);
            CP16(smemA(&As[buf][row][cq]), &pf16[(size_t)gr * FDIM + kc + cq]);
        }
#pragma unroll
        for (int i = 0; i < 2; i++) {
            int id = tid + i * 256;
            int row = id >> 2, cq = (id & 3) * 8;
            CP16(smemA(&Bs[buf][row][cq]), &GT[(size_t)(nb + row) * FDIM + kc + cq]);
        }
        CPCOMMIT();
    };

    float acc[2][8][4] = {};
    loadTiles(0, 0);
    const int NT = FDIM / 32;
    for (int t = 0; t < NT; t++) {
        int buf = t & 1;
        if (t + 1 < NT) { loadTiles(buf ^ 1, (t + 1) * 32); CPWAIT1(); }
        else CPWAIT0();
        __syncthreads();
#pragma unroll
        for (int ks = 0; ks < 2; ks++) {
            int k0 = ks * 16;
            unsigned a[2][4], b[8][2];
#pragma unroll
            for (int mt = 0; mt < 2; mt++) {
                int r = warpM + mt * 16;
                a[mt][0] = *(const unsigned*)&As[buf][r + g][k0 + 2 * t4];
                a[mt][1] = *(const unsigned*)&As[buf][r + g + 8][k0 + 2 * t4];
                a[mt][2] = *(const unsigned*)&As[buf][r + g][k0 + 2 * t4 + 8];
                a[mt][3] = *(const unsigned*)&As[buf][r + g + 8][k0 + 2 * t4 + 8];
            }
#pragma unroll
            for (int nt = 0; nt < 8; nt++) {
                b[nt][0] = *(const unsigned*)&Bs[buf][warpN + nt * 8 + g][k0 + 2 * t4];
                b[nt][1] = *(const unsigned*)&Bs[buf][warpN + nt * 8 + g][k0 + 2 * t4 + 8];
            }
#pragma unroll
            for (int mt = 0; mt < 2; mt++)
#pragma unroll
                for (int nt = 0; nt < 8; nt++) mma_f16(acc[mt][nt], a[mt], b[nt]);
        }
        __syncthreads();
    }
#pragma unroll
    for (int mt = 0; mt < 2; mt++) {
#pragma unroll
        for (int nt = 0; nt < 8; nt++) {
            int col = nb + warpN + nt * 8 + t4 * 2;
            float b0 = bias[col], b1 = bias[col + 1];
            int r0 = mb + warpM + mt * 16 + g, r1 = r0 + 8;
            if (r0 < NN) {
                float g0 = fsigmoid(acc[mt][nt][0] + b0);
                float g1 = fsigmoid(acc[mt][nt][1] + b1);
                float2 x = h2(&X16[(size_t)r0 * FDIM + col]);
                float2 p = h2(&pf16[(size_t)r0 * FDIM + col]);
                float2 o = {g0 * x.x + (1.f - g0) * p.x, g1 * x.y + (1.f - g1) * p.y};
                *(float2*)&out[(size_t)r0 * (2 * FDIM) + dual * FDIM + col] = o;
            }
            if (r1 < NN) {
                float g0 = fsigmoid(acc[mt][nt][2] + b0);
                float g1 = fsigmoid(acc[mt][nt][3] + b1);
                float2 x = h2(&X16[(size_t)r1 * FDIM + col]);
                float2 p = h2(&pf16[(size_t)r1 * FDIM + col]);
                float2 o = {g0 * x.x + (1.f - g0) * p.x, g1 * x.y + (1.f - g1) * p.y};
                *(float2*)&out[(size_t)r1 * (2 * FDIM) + dual * FDIM + col] = o;
            }
        }
    }
}

// ---------------- launch ----------------
extern "C" void kernel_launch(void* const* d_in, const int* in_sizes, int n_in,
                              void* d_out, int out_size) {
    const float* ent     = (const float*)d_in[0];
    const float* rel     = (const float*)d_in[1];
    const int*   esrc    = (const int*)d_in[2];
    const int*   edst    = (const int*)d_in[3];
    const int*   erel    = (const int*)d_in[4];
    const float* attn_e  = (const float*)d_in[5];
    const float* gate_e  = (const float*)d_in[6];
    const float* proxy_e = (const float*)d_in[7];
    const float* bias_e  = (const float*)d_in[8];
    const float* attn_r  = (const float*)d_in[9];
    const float* gate_r  = (const float*)d_in[10];
    const float* proxy_r = (const float*)d_in[11];
    const float* bias_r  = (const float*)d_in[12];
    float* out = (float*)d_out;

    cudaFuncSetAttribute(k_gemm12, cudaFuncAttributeMaxDynamicSharedMemorySize, G12_SMEM);

    k_prep<<<25000, 256>>>(ent, rel, gate_e, gate_r);
    k_hist<<<3125, 256>>>(edst);
    k_scan<<<1, 1024>>>();
    k_scatter<<<3125, 256>>>(esrc, edst, erel);
    k_relnorm<<<RR, FF>>>(rel, attn_e, attn_r);
    k_init<<<6250, 256>>>();
    k_layer<<<6250, 256>>>(0);
    k_layer<<<6250, 256>>>(1);
    k_proxyn<<<128, FDIM>>>(proxy_e, proxy_r);
    k_gemm12<<<dim3(391, 1, 2), 256, G12_SMEM>>>();
    k_gemm3t<<<dim3(391, 3, 2), 256>>>(bias_e, bias_r, out);
}